// round 3
// baseline (speedup 1.0000x reference)
#include <cuda_runtime.h>
#include <cuda_bf16.h>

// Problem constants
#define BB   4
#define SS   1024
#define EE   1024
#define HH   16
#define DD   64
#define PP   1024
#define NSS  2048          // P + S
#define E3   3072          // 3*E

// ---------------------------------------------------------------------------
// Scratch (static __device__ arrays: the sanctioned no-alloc workaround)
// ---------------------------------------------------------------------------
__device__ float g_qkv[(size_t)BB * SS * E3];            // 50.3 MB  [B*S, 3E]
__device__ float g_scores[(size_t)BB * HH * SS * NSS];   // 536 MB   [B*H, S, NS]
__device__ float g_attn[(size_t)BB * SS * EE];           // 16.8 MB  [B*S, E] merged heads

// ---------------------------------------------------------------------------
// Generic tiled GEMM with bias:  C[M,N] = A[M,K] @ B[K,N] + bias[N]
// BM=128, BN=128, BK=16, 256 threads, 8x8 microtile.
// ---------------------------------------------------------------------------
template<int N, int K>
__device__ __forceinline__ void gemm_bias_body(
    const float* __restrict__ A, const float* __restrict__ B,
    const float* __restrict__ bias, float* __restrict__ C)
{
    __shared__ float As[16][132];   // transposed A tile [k][m], pad 4 (float4-aligned)
    __shared__ float Bs[16][128];   // B tile [k][n]

    const int tid = threadIdx.x;
    const int tr  = tid >> 4;       // 0..15 (row group)
    const int tc  = tid & 15;       // 0..15 (col group)
    const int m0  = blockIdx.y * 128;
    const int n0  = blockIdx.x * 128;

    float acc[8][8];
#pragma unroll
    for (int i = 0; i < 8; i++)
#pragma unroll
        for (int j = 0; j < 8; j++) acc[i][j] = 0.f;

    for (int k0 = 0; k0 < K; k0 += 16) {
        // Load A tile 128x16 -> transposed
#pragma unroll
        for (int it = 0; it < 2; it++) {
            int f   = tid + it * 256;        // 0..511 float4 idx
            int row = f >> 2;                // 0..127
            int kq  = (f & 3) * 4;           // 0,4,8,12
            float4 v = *reinterpret_cast<const float4*>(&A[(size_t)(m0 + row) * K + k0 + kq]);
            As[kq + 0][row] = v.x; As[kq + 1][row] = v.y;
            As[kq + 2][row] = v.z; As[kq + 3][row] = v.w;
        }
        // Load B tile 16x128 directly
#pragma unroll
        for (int it = 0; it < 2; it++) {
            int f    = tid + it * 256;
            int krow = f >> 5;               // 0..15
            int nc   = (f & 31) * 4;         // 0..124
            *reinterpret_cast<float4*>(&Bs[krow][nc]) =
                *reinterpret_cast<const float4*>(&B[(size_t)(k0 + krow) * N + n0 + nc]);
        }
        __syncthreads();

#pragma unroll
        for (int k = 0; k < 16; k++) {
            float4 a0 = *reinterpret_cast<const float4*>(&As[k][tr * 8]);
            float4 a1 = *reinterpret_cast<const float4*>(&As[k][tr * 8 + 4]);
            float4 b0 = *reinterpret_cast<const float4*>(&Bs[k][tc * 8]);
            float4 b1 = *reinterpret_cast<const float4*>(&Bs[k][tc * 8 + 4]);
            float a[8] = {a0.x, a0.y, a0.z, a0.w, a1.x, a1.y, a1.z, a1.w};
            float b[8] = {b0.x, b0.y, b0.z, b0.w, b1.x, b1.y, b1.z, b1.w};
#pragma unroll
            for (int i = 0; i < 8; i++)
#pragma unroll
                for (int j = 0; j < 8; j++)
                    acc[i][j] = fmaf(a[i], b[j], acc[i][j]);
        }
        __syncthreads();
    }

#pragma unroll
    for (int i = 0; i < 8; i++) {
        int m = m0 + tr * 8 + i;
#pragma unroll
        for (int j = 0; j < 8; j += 4) {
            int n = n0 + tc * 8 + j;
            float4 o;
            o.x = acc[i][j + 0] + bias[n + 0];
            o.y = acc[i][j + 1] + bias[n + 1];
            o.z = acc[i][j + 2] + bias[n + 2];
            o.w = acc[i][j + 3] + bias[n + 3];
            *reinterpret_cast<float4*>(&C[(size_t)m * N + n]) = o;
        }
    }
}

__global__ __launch_bounds__(256) void gemm_qkv_kernel(
    const float* __restrict__ x, const float* __restrict__ w, const float* __restrict__ b)
{
    gemm_bias_body<E3, EE>(x, w, b, g_qkv);
}

__global__ __launch_bounds__(256) void gemm_proj_kernel(
    const float* __restrict__ w, const float* __restrict__ b, float* __restrict__ out)
{
    gemm_bias_body<EE, EE>(g_attn, w, b, out);
}

// ---------------------------------------------------------------------------
// present[kv,b,h,n,d]: n<P from layer_past, n>=P from qkv (k at +E, v at +2E)
// Operates in float4 units (D=64 -> 16 float4 per row).
// ---------------------------------------------------------------------------
__global__ __launch_bounds__(256) void present_kernel(
    const float* __restrict__ past, float* __restrict__ present)
{
    int idx = blockIdx.x * 256 + threadIdx.x;   // float4 index, total 2*B*H*NS*16
    int d4 = idx & 15;
    int t  = idx >> 4;
    int n  = t & (NSS - 1);  t >>= 11;
    int h  = t & (HH - 1);   t >>= 4;
    int b  = t & (BB - 1);
    int kv = t >> 2;

    float4 v;
    if (n < PP) {
        size_t src = ((((size_t)kv * BB + b) * HH + h) * PP + n) * 16 + d4;
        v = reinterpret_cast<const float4*>(past)[src];
    } else {
        int s = n - PP;
        v = *reinterpret_cast<const float4*>(
            &g_qkv[((size_t)(b * SS + s)) * E3 + (kv + 1) * EE + h * DD + d4 * 4]);
    }
    reinterpret_cast<float4*>(present)[idx] = v;
}

// ---------------------------------------------------------------------------
// Scores:  S[bh, q, k] = (Q . K) * 1/8, causal-masked to -10000.
// Block = 64q x 64k tile; one pass over D=64 held in smem (transposed [d][row]).
// ---------------------------------------------------------------------------
__global__ __launch_bounds__(256) void scores_kernel(const float* __restrict__ presentK)
{
    __shared__ float Qst[64][68];   // [d][q]
    __shared__ float Kst[64][68];   // [d][k]

    const int tid = threadIdx.x;
    const int kb  = blockIdx.x * 64;
    const int qb  = blockIdx.y * 64;
    const int bh  = blockIdx.z;
    const int b   = bh >> 4;
    const int h   = bh & 15;

    float* srow = g_scores + ((size_t)bh * SS + qb) * NSS + kb;

    if (kb > PP + qb + 63) {  // fully masked tile
        const float4 mneg = make_float4(-10000.f, -10000.f, -10000.f, -10000.f);
        for (int f = tid; f < 64 * 16; f += 256) {
            int r = f >> 4, c = (f & 15) * 4;
            *reinterpret_cast<float4*>(&srow[(size_t)r * NSS + c]) = mneg;
        }
        return;
    }

    const float* Q  = g_qkv + ((size_t)(b * SS + qb)) * E3 + h * DD;
    const float* Kp = presentK + ((size_t)bh * NSS + kb) * DD;

#pragma unroll
    for (int it = 0; it < 4; it++) {
        int f = tid + it * 256, row = f >> 4, c4 = (f & 15) * 4;
        float4 v = *reinterpret_cast<const float4*>(&Q[(size_t)row * E3 + c4]);
        Qst[c4 + 0][row] = v.x; Qst[c4 + 1][row] = v.y;
        Qst[c4 + 2][row] = v.z; Qst[c4 + 3][row] = v.w;
    }
#pragma unroll
    for (int it = 0; it < 4; it++) {
        int f = tid + it * 256, row = f >> 4, c4 = (f & 15) * 4;
        float4 v = *reinterpret_cast<const float4*>(&Kp[(size_t)row * DD + c4]);
        Kst[c4 + 0][row] = v.x; Kst[c4 + 1][row] = v.y;
        Kst[c4 + 2][row] = v.z; Kst[c4 + 3][row] = v.w;
    }
    __syncthreads();

    const int tr = tid >> 4, tc = tid & 15;
    float acc[4][4];
#pragma unroll
    for (int i = 0; i < 4; i++)
#pragma unroll
        for (int j = 0; j < 4; j++) acc[i][j] = 0.f;

#pragma unroll
    for (int d = 0; d < 64; d++) {
        float4 a = *reinterpret_cast<const float4*>(&Qst[d][tr * 4]);
        float4 k4 = *reinterpret_cast<const float4*>(&Kst[d][tc * 4]);
        float av[4] = {a.x, a.y, a.z, a.w};
        float bv[4] = {k4.x, k4.y, k4.z, k4.w};
#pragma unroll
        for (int i = 0; i < 4; i++)
#pragma unroll
            for (int j = 0; j < 4; j++)
                acc[i][j] = fmaf(av[i], bv[j], acc[i][j]);
    }

    const float scale = 0.125f;   // 1/sqrt(64)
#pragma unroll
    for (int r = 0; r < 4; r++) {
        int q   = qb + tr * 4 + r;
        int lim = PP + q;                 // keys j <= lim allowed
        int kc  = kb + tc * 4;
        float4 o;
        o.x = (kc + 0 <= lim) ? acc[r][0] * scale : -10000.f;
        o.y = (kc + 1 <= lim) ? acc[r][1] * scale : -10000.f;
        o.z = (kc + 2 <= lim) ? acc[r][2] * scale : -10000.f;
        o.w = (kc + 3 <= lim) ? acc[r][3] * scale : -10000.f;
        *reinterpret_cast<float4*>(&srow[(size_t)(tr * 4 + r) * NSS + tc * 4]) = o;
    }
}

// ---------------------------------------------------------------------------
// Row softmax over 2048 elements (in place). 1 block = 1 row, 256 threads.
// ---------------------------------------------------------------------------
__global__ __launch_bounds__(256) void softmax_kernel()
{
    float* p = g_scores + (size_t)blockIdx.x * NSS;
    const int tid = threadIdx.x;

    float4 a = reinterpret_cast<const float4*>(p)[tid];
    float4 b = reinterpret_cast<const float4*>(p)[tid + 256];

    float m = fmaxf(fmaxf(fmaxf(a.x, a.y), fmaxf(a.z, a.w)),
                    fmaxf(fmaxf(b.x, b.y), fmaxf(b.z, b.w)));
#pragma unroll
    for (int o = 16; o; o >>= 1) m = fmaxf(m, __shfl_xor_sync(0xffffffffu, m, o));

    __shared__ float wmax[8];
    __shared__ float wsum[8];
    if ((tid & 31) == 0) wmax[tid >> 5] = m;
    __syncthreads();
    float mm = wmax[0];
#pragma unroll
    for (int i = 1; i < 8; i++) mm = fmaxf(mm, wmax[i]);

    a.x = __expf(a.x - mm); a.y = __expf(a.y - mm);
    a.z = __expf(a.z - mm); a.w = __expf(a.w - mm);
    b.x = __expf(b.x - mm); b.y = __expf(b.y - mm);
    b.z = __expf(b.z - mm); b.w = __expf(b.w - mm);

    float s = a.x + a.y + a.z + a.w + b.x + b.y + b.z + b.w;
#pragma unroll
    for (int o = 16; o; o >>= 1) s += __shfl_xor_sync(0xffffffffu, s, o);
    if ((tid & 31) == 0) wsum[tid >> 5] = s;
    __syncthreads();
    float ss = 0.f;
#pragma unroll
    for (int i = 0; i < 8; i++) ss += wsum[i];

    float r = 1.f / ss;
    a.x *= r; a.y *= r; a.z *= r; a.w *= r;
    b.x *= r; b.y *= r; b.z *= r; b.w *= r;
    reinterpret_cast<float4*>(p)[tid]       = a;
    reinterpret_cast<float4*>(p)[tid + 256] = b;
}

// ---------------------------------------------------------------------------
// PV: attn[b, q, h*64 + d] = probs[bh, q, :] @ V[bh, :, d]
// Block = 64q x 64d (full head dim), BK=32, causal upper bound on k loop.
// ---------------------------------------------------------------------------
__global__ __launch_bounds__(256) void pv_kernel(const float* __restrict__ presentV)
{
    __shared__ float Pst[32][68];   // [k][q]
    __shared__ float Vs[32][68];    // [k][d]

    const int tid = threadIdx.x;
    const int qb  = blockIdx.x * 64;
    const int bh  = blockIdx.y;
    const int b   = bh >> 4;
    const int h   = bh & 15;

    const float* Prow = g_scores + ((size_t)bh * SS + qb) * NSS;
    const float* V    = presentV + (size_t)bh * NSS * DD;

    const int tr = tid >> 4, tc = tid & 15;
    float acc[4][4];
#pragma unroll
    for (int i = 0; i < 4; i++)
#pragma unroll
        for (int j = 0; j < 4; j++) acc[i][j] = 0.f;

    const int kmax = PP + qb + 64;   // multiple of 32; probs beyond are exactly 0

    for (int k0 = 0; k0 < kmax; k0 += 32) {
#pragma unroll
        for (int it = 0; it < 2; it++) {
            int f = tid + it * 256, row = f >> 3, c4 = (f & 7) * 4;
            float4 v = *reinterpret_cast<const float4*>(&Prow[(size_t)row * NSS + k0 + c4]);
            Pst[c4 + 0][row] = v.x; Pst[c4 + 1][row] = v.y;
            Pst[c4 + 2][row] = v.z; Pst[c4 + 3][row] = v.w;
        }
#pragma unroll
        for (int it = 0; it < 2; it++) {
            int f = tid + it * 256, row = f >> 4, c4 = (f & 15) * 4;
            *reinterpret_cast<float4*>(&Vs[row][c4]) =
                *reinterpret_cast<const float4*>(&V[(size_t)(k0 + row) * DD + c4]);
        }
        __syncthreads();

#pragma unroll
        for (int k = 0; k < 32; k++) {
            float4 a = *reinterpret_cast<const float4*>(&Pst[k][tr * 4]);
            float4 v4 = *reinterpret_cast<const float4*>(&Vs[k][tc * 4]);
            float av[4] = {a.x, a.y, a.z, a.w};
            float vv[4] = {v4.x, v4.y, v4.z, v4.w};
#pragma unroll
            for (int i = 0; i < 4; i++)
#pragma unroll
                for (int j = 0; j < 4; j++)
                    acc[i][j] = fmaf(av[i], vv[j], acc[i][j]);
        }
        __syncthreads();
    }

#pragma unroll
    for (int r = 0; r < 4; r++) {
        float4 o = make_float4(acc[r][0], acc[r][1], acc[r][2], acc[r][3]);
        size_t off = ((size_t)(b * SS + qb + tr * 4 + r)) * EE + h * DD + tc * 4;
        *reinterpret_cast<float4*>(&g_attn[off]) = o;
    }
}

// ---------------------------------------------------------------------------
// Launch. Output layout: [ out (B*S*E) | present (2*B*H*NS*D) ]
// ---------------------------------------------------------------------------
extern "C" void kernel_launch(void* const* d_in, const int* in_sizes, int n_in,
                              void* d_out, int out_size)
{
    (void)in_sizes; (void)n_in; (void)out_size;
    const float* x      = (const float*)d_in[0];
    const float* past   = (const float*)d_in[1];
    const float* w_attn = (const float*)d_in[2];
    const float* b_attn = (const float*)d_in[3];
    const float* w_proj = (const float*)d_in[4];
    const float* b_proj = (const float*)d_in[5];

    float* out      = (float*)d_out;
    float* present  = out + (size_t)BB * SS * EE;           // offset 4194304
    float* presentK = present;
    float* presentV = present + (size_t)BB * HH * NSS * DD; // +8388608

    // 1) QKV = x @ w_attn + b_attn
    gemm_qkv_kernel<<<dim3(E3 / 128, (BB * SS) / 128), 256>>>(x, w_attn, b_attn);

    // 2) present = concat(past, new K/V)
    {
        int n4 = 2 * BB * HH * NSS * (DD / 4);   // 4,194,304 float4
        present_kernel<<<n4 / 256, 256>>>(past, present);
    }

    // 3) scores = mask(QK^T / sqrt(D))
    scores_kernel<<<dim3(NSS / 64, SS / 64, BB * HH), 256>>>(presentK);

    // 4) row softmax
    softmax_kernel<<<BB * HH * SS, 256>>>();

    // 5) attn = probs @ V  (merged-head layout)
    pv_kernel<<<dim3(SS / 64, BB * HH), 256>>>(presentV);

    // 6) out = attn @ w_proj + b_proj
    gemm_proj_kernel<<<dim3(EE / 128, (BB * SS) / 128), 256>>>(w_proj, b_proj, out);
}